// round 12
// baseline (speedup 1.0000x reference)
#include <cuda_runtime.h>
#include <cuda_fp16.h>
#include <math.h>

#define NROWS 32768
#define NC 1000
#define SLOT_BYTES 4000          // one row of logits
#define DEPTH 2                  // per-warp pipeline depth
#define WARPS_PER_CTA 4
#define GRID_ROWK 1024           // single wave: 7 CTAs/SM x 148 = 1036 >= 1024
#define NTRANS 512               // transposer CTAs (bid < 512), 2 tiles each
#define TOTW (GRID_ROWK * WARPS_PER_CTA)
#define ROWS_PER_WARP (NROWS / TOTW)   // 8
#define FIXSCALE 268435456.0     // 2^28

// Scratch (allocation-free device globals, zero-initialized at module load).
// Tt padded for unpredicated loads.
__device__ __align__(16) __half g_Tth[NC * NC + 32];
__device__ unsigned long long g_sum;
__device__ unsigned int g_done;
__device__ unsigned int g_ready;

// ---------------------------------------------------------------------------
// helpers
// ---------------------------------------------------------------------------
__device__ __forceinline__ unsigned int smem_u32(const void* p) {
    unsigned int a;
    asm("{ .reg .u64 t; cvta.to.shared.u64 t, %1; cvt.u32.u64 %0, t; }"
        : "=r"(a) : "l"(p));
    return a;
}
__device__ __forceinline__ void mbar_init(unsigned int mbar, unsigned int cnt) {
    asm volatile("mbarrier.init.shared.b64 [%0], %1;" :: "r"(mbar), "r"(cnt) : "memory");
}
__device__ __forceinline__ void mbar_wait(unsigned int mbar, int phase) {
    asm volatile(
        "{\n\t.reg .pred P;\n\t"
        "W_%=: mbarrier.try_wait.parity.acquire.cta.shared::cta.b64 P, [%0], %1, 0x989680;\n\t"
        "@P bra D_%=;\n\t"
        "bra W_%=;\n\t"
        "D_%=:\n\t}"
        :: "r"(mbar), "r"(phase) : "memory");
}
__device__ __forceinline__ void bulk_load(unsigned int dst, const void* src,
                                          unsigned int bytes, unsigned int mbar) {
    asm volatile("mbarrier.arrive.expect_tx.shared.b64 _, [%0], %1;"
                 :: "r"(mbar), "r"(bytes) : "memory");
    asm volatile(
        "cp.async.bulk.shared::cluster.global.mbarrier::complete_tx::bytes "
        "[%0], [%1], %2, [%3];"
        :: "r"(dst), "l"(src), "r"(bytes), "r"(mbar) : "memory");
}
__device__ __forceinline__ unsigned int ld_acquire(const unsigned int* p) {
    unsigned int v;
    asm volatile("ld.acquire.gpu.b32 %0, [%1];" : "=r"(v) : "l"(p) : "memory");
    return v;
}

// ---------------------------------------------------------------------------
// Single fused kernel.
// Phase A (bid<512): transpose 2 tiles of T -> fp16 g_Tth (smem reused from
//           the pipeline buffers, before any bulk load), fence, signal.
// Phase B (all):     issue prologue bulk loads + label prefetch (independent
//           of Tt), then spin until g_ready==NTRANS.
// Phase C:  R11 main loop (per-warp depth-2 pipelines, no block barriers).
// Epilogue: u64 fixed-point atomic; last-ticket CTA writes out and resets
//           globals for the next graph replay.
// ---------------------------------------------------------------------------
__global__ __launch_bounds__(128) void fused_k(const float* __restrict__ logits,
                                               const float* __restrict__ T,
                                               const void* __restrict__ target,
                                               float* __restrict__ outp) {
    __shared__ __align__(128) char buf[WARPS_PER_CTA][DEPTH][SLOT_BYTES];
    __shared__ __align__(8) unsigned long long mbars[WARPS_PER_CTA][DEPTH];
    __shared__ unsigned long long s_part[WARPS_PER_CTA];

    const int tid  = threadIdx.x;
    const int lane = tid & 31;
    const int warp = tid >> 5;
    const int gw   = blockIdx.x * WARPS_PER_CTA + warp;

    // ---- Phase A: transpose (CTAs 0..511), smem tile overlaps buf ----
    if (blockIdx.x < NTRANS) {
        float* tile = reinterpret_cast<float*>(&buf[0][0][0]);  // 32x33 floats
        const int tx = tid & 31, ty = tid >> 5;                 // 4 row-threads
#pragma unroll
        for (int t = 0; t < 2; t++) {
            const int tb = blockIdx.x + t * NTRANS;
            const int bx = tb & 31, by = tb >> 5;
            int x = bx * 32 + tx;
#pragma unroll
            for (int j = 0; j < 32; j += 4) {
                int y = by * 32 + ty + j;
                if (x < NC && y < NC)
                    tile[(ty + j) * 33 + tx] = T[y * NC + x];
            }
            __syncthreads();
            int x2 = by * 32 + tx;
#pragma unroll
            for (int j = 0; j < 32; j += 4) {
                int y2 = bx * 32 + ty + j;
                if (x2 < NC && y2 < NC)
                    g_Tth[(size_t)y2 * NC + x2] = __float2half_rn(tile[tx * 33 + ty + j]);
            }
            __syncthreads();
        }
        __threadfence();
        if (tid == 0) atomicAdd(&g_ready, 1u);
    }

    // ---- mbarrier init ----
    if (tid < WARPS_PER_CTA * DEPTH)
        mbar_init(smem_u32(&mbars[tid / DEPTH][tid % DEPTH]), 1);
    __syncthreads();

    const unsigned int mb_base = smem_u32(&mbars[warp][0]);
    const unsigned int sb_base = smem_u32(&buf[warp][0][0]);

    // ---- Phase B: prologue loads (independent of Tt) ----
    if (lane == 0) {
#pragma unroll
        for (int s = 0; s < DEPTH; s++)
            bulk_load(sb_base + s * SLOT_BYTES,
                      logits + (size_t)(gw + s * TOTW) * NC, SLOT_BYTES,
                      mb_base + s * 8);
    }

    // Per-warp dtype detection on the first 8 labels (deterministic;
    // P(int32 data passing as int64) ~ 1e-12).
    int is64 = 0, ynext = 0;
    if (lane == 0) {
        const uint4* t4 = (const uint4*)target;
        uint4 a = t4[0], b = t4[1];
        is64 = ((a.y | a.w | b.y | b.w) == 0u) ? 1 : 0;
        int yy = is64 ? (int)((const long long*)target)[gw]
                      : ((const int*)target)[gw];
        ynext = yy < 0 ? 0 : (yy >= NC ? NC - 1 : yy);
    }

    // Spin until all transposer CTAs have published g_Tth.
    if (tid == 0) {
        while (ld_acquire(&g_ready) < NTRANS) __nanosleep(64);
    }
    __syncthreads();

    // ---- Phase C: main loop (identical to R11) ----
    unsigned long long acc = 0ull;
    int s = 0, ph = 0;

    for (int k = 0; k < ROWS_PER_WARP; k++) {
        const int row = gw + k * TOTW;
        const int y = __shfl_sync(0xffffffffu, ynext, 0);

        // Tt LDGs issued BEFORE the wait (L2 latency overlaps DRAM wait).
        const uint2* tt2 = reinterpret_cast<const uint2*>(g_Tth + (size_t)y * NC);
        uint2 tw[8];
#pragma unroll
        for (int j = 0; j < 8; j++) tw[j] = tt2[lane + 32 * j];

        // Prefetch next label (also before the wait).
        if (lane == 0 && k + 1 < ROWS_PER_WARP) {
            int i2 = gw + (k + 1) * TOTW;
            int yy = is64 ? (int)((const long long*)target)[i2]
                          : ((const int*)target)[i2];
            ynext = yy < 0 ? 0 : (yy >= NC ? NC - 1 : yy);
        }

        const unsigned int mb   = mb_base + s * 8;
        const char*        slot = &buf[warp][0][0] + s * SLOT_BYTES;
        mbar_wait(mb, ph);

        // Target logit from smem (lane 0, broadcast).
        const float ly = __shfl_sync(0xffffffffu,
            lane == 0 ? *reinterpret_cast<const float*>(slot + (size_t)y * 4) : 0.f, 0);

        // Fused Z / D from smem + Tt registers.
        const float4* r4 = reinterpret_cast<const float4*>(slot);
        float Z = 0.f, D = 0.f;
#pragma unroll
        for (int j = 0; j < 8; j++) {
            int idx = lane + 32 * j;
            if (idx < NC / 4) {
                float4 v = r4[idx];
                float e0 = __expf(v.x);
                float e1 = __expf(v.y);
                float e2 = __expf(v.z);
                float e3 = __expf(v.w);
                Z += (e0 + e1) + (e2 + e3);
                float2 t01 = __half22float2(*reinterpret_cast<__half2*>(&tw[j].x));
                float2 t23 = __half22float2(*reinterpret_cast<__half2*>(&tw[j].y));
                D = fmaf(e0, t01.x, fmaf(e1, t01.y, fmaf(e2, t23.x, fmaf(e3, t23.y, D))));
            }
        }
#pragma unroll
        for (int o = 16; o > 0; o >>= 1) {
            Z += __shfl_xor_sync(0xffffffffu, Z, o);
            D += __shfl_xor_sync(0xffffffffu, D, o);
        }
        if (lane == 0) {
            float lse = __logf(Z);
            float ey  = __expf(ly);
            float val = (ey / D) * (lse - ly);   // beta * ce
            acc += (unsigned long long)__double2ll_rn((double)val * FIXSCALE);
        }

        // Recycle this slot (private to this warp): row k+DEPTH.
        if (lane == 0 && k + DEPTH < ROWS_PER_WARP)
            bulk_load(sb_base + s * SLOT_BYTES,
                      logits + (size_t)(row + DEPTH * TOTW) * NC, SLOT_BYTES, mb);

        if (++s == DEPTH) { s = 0; ph ^= 1; }
    }

    // ---- Epilogue: deterministic integer reduction + self-reset ----
    if (lane == 0) s_part[warp] = acc;
    __syncthreads();
    if (tid == 0) {
        unsigned long long tot = 0ull;
#pragma unroll
        for (int w = 0; w < WARPS_PER_CTA; w++) tot += s_part[w];
        atomicAdd(&g_sum, tot);
        __threadfence();
        unsigned int ticket = atomicAdd(&g_done, 1u);
        if (ticket == (unsigned)(gridDim.x - 1)) {
            unsigned long long v = atomicAdd(&g_sum, 0ull);
            outp[0] = (float)((double)v / FIXSCALE / (double)NROWS);
            // reset for next graph replay (kernel boundary publishes these)
            g_sum = 0ull;
            g_done = 0u;
            g_ready = 0u;
        }
    }
}

extern "C" void kernel_launch(void* const* d_in, const int* in_sizes, int n_in,
                              void* d_out, int out_size) {
    const float* logits = (const float*)d_in[0];   // [N, C] f32
    const float* T      = (const float*)d_in[1];   // [C, C] f32
    const void*  target = d_in[2];                 // [N] int32 or int64
    float*       out    = (float*)d_out;

    fused_k<<<GRID_ROWK, 128>>>(logits, T, target, out);
}

// round 14
// speedup vs baseline: 1.1168x; 1.1168x over previous
#include <cuda_runtime.h>
#include <cuda_fp16.h>
#include <math.h>

#define NROWS 32768
#define NC 1000
#define SLOT_BYTES 4000          // one row of logits
#define DEPTH 2                  // per-warp pipeline depth
#define WARPS_PER_CTA 4
#define GRID_ROWK 1024           // 4096 warps x 8 rows; 7 CTAs/SM
#define TOTW (GRID_ROWK * WARPS_PER_CTA)
#define ROWS_PER_WARP (NROWS / TOTW)   // 8
#define FIXSCALE 268435456.0     // 2^28

// Scratch (allocation-free device globals). Tt padded for unpredicated loads.
__device__ __align__(16) __half g_Tth[NC * NC + 32];
__device__ unsigned long long g_sum;
__device__ unsigned int g_done;
__device__ int g_is64;

// ---------------------------------------------------------------------------
// Kernel 1: blocks 0..1023 transpose T -> fp16; block 1024 detects target
// dtype (first 4096 labels: conclusive) and resets accumulator + ticket.
// ---------------------------------------------------------------------------
__global__ __launch_bounds__(256) void prep_k(const float* __restrict__ T,
                                              const uint4* __restrict__ tgt) {
    if (blockIdx.x < 1024) {
        __shared__ float tile[32][33];
        const int bx = blockIdx.x & 31, by = blockIdx.x >> 5;
        const int tx = threadIdx.x & 31, ty = threadIdx.x >> 5;
        int x = bx * 32 + tx;
#pragma unroll
        for (int j = 0; j < 32; j += 8) {
            int y = by * 32 + ty + j;
            if (x < NC && y < NC)
                tile[ty + j][tx] = T[y * NC + x];
        }
        __syncthreads();
        int x2 = by * 32 + tx;
#pragma unroll
        for (int j = 0; j < 32; j += 8) {
            int y2 = bx * 32 + ty + j;
            if (x2 < NC && y2 < NC)
                g_Tth[(size_t)y2 * NC + x2] = __float2half_rn(tile[tx][ty + j]);
        }
    } else {
        unsigned int acc = 0;
#pragma unroll
        for (int k = 0; k < 8; k++) {
            uint4 w = tgt[threadIdx.x + 256 * k];
            acc |= w.y | w.w;
        }
#pragma unroll
        for (int o = 16; o > 0; o >>= 1)
            acc |= __shfl_xor_sync(0xffffffffu, acc, o);
        __shared__ unsigned int s[8];
        if ((threadIdx.x & 31) == 0) s[threadIdx.x >> 5] = acc;
        __syncthreads();
        if (threadIdx.x == 0) {
            unsigned int a = 0;
#pragma unroll
            for (int w = 0; w < 8; w++) a |= s[w];
            g_is64 = (a == 0u) ? 1 : 0;
            g_sum = 0ull;
            g_done = 0u;
        }
    }
}

// ---------------------------------------------------------------------------
// helpers
// ---------------------------------------------------------------------------
__device__ __forceinline__ unsigned int smem_u32(const void* p) {
    unsigned int a;
    asm("{ .reg .u64 t; cvta.to.shared.u64 t, %1; cvt.u32.u64 %0, t; }"
        : "=r"(a) : "l"(p));
    return a;
}
__device__ __forceinline__ void mbar_init(unsigned int mbar, unsigned int cnt) {
    asm volatile("mbarrier.init.shared.b64 [%0], %1;" :: "r"(mbar), "r"(cnt) : "memory");
}
__device__ __forceinline__ void mbar_wait(unsigned int mbar, int phase) {
    asm volatile(
        "{\n\t.reg .pred P;\n\t"
        "W_%=: mbarrier.try_wait.parity.acquire.cta.shared::cta.b64 P, [%0], %1, 0x989680;\n\t"
        "@P bra D_%=;\n\t"
        "bra W_%=;\n\t"
        "D_%=:\n\t}"
        :: "r"(mbar), "r"(phase) : "memory");
}
__device__ __forceinline__ void bulk_load(unsigned int dst, const void* src,
                                          unsigned int bytes, unsigned int mbar) {
    asm volatile("mbarrier.arrive.expect_tx.shared.b64 _, [%0], %1;"
                 :: "r"(mbar), "r"(bytes) : "memory");
    asm volatile(
        "cp.async.bulk.shared::cluster.global.mbarrier::complete_tx::bytes "
        "[%0], [%1], %2, [%3];"
        :: "r"(dst), "l"(src), "r"(bytes), "r"(mbar) : "memory");
}

// ---------------------------------------------------------------------------
// Kernel 2: per-warp depth-2 pipelines at 7 CTAs/SM (28 warps/SM).
// No __syncthreads in the main loop; Tt LDGs + next label issued BEFORE the
// mbarrier wait. Label + target logit via all-lane broadcast loads (no SHFL).
// ---------------------------------------------------------------------------
__global__ __launch_bounds__(128) void row_k(const float* __restrict__ logits,
                                             const void* __restrict__ target,
                                             float* __restrict__ outp) {
    __shared__ __align__(128) char buf[WARPS_PER_CTA][DEPTH][SLOT_BYTES];
    __shared__ __align__(8) unsigned long long mbars[WARPS_PER_CTA][DEPTH];
    __shared__ unsigned long long s_part[WARPS_PER_CTA];

    const int tid  = threadIdx.x;
    const int lane = tid & 31;
    const int warp = tid >> 5;
    const int gw   = blockIdx.x * WARPS_PER_CTA + warp;
    const int is64 = g_is64;

    const unsigned int mb_base = smem_u32(&mbars[warp][0]);
    const unsigned int sb_base = smem_u32(&buf[warp][0][0]);

    if (tid < WARPS_PER_CTA * DEPTH)
        mbar_init(smem_u32(&mbars[tid / DEPTH][tid % DEPTH]), 1);
    __syncthreads();

    // Prologue: lane 0 fills both slots for this warp.
    if (lane == 0) {
#pragma unroll
        for (int s = 0; s < DEPTH; s++)
            bulk_load(sb_base + s * SLOT_BYTES,
                      logits + (size_t)(gw + s * TOTW) * NC, SLOT_BYTES,
                      mb_base + s * 8);
    }

    // Label for k=0: all lanes load the same address (1-sector broadcast).
    int ynext = is64 ? (int)((const long long*)target)[gw]
                     : ((const int*)target)[gw];
    ynext = ynext < 0 ? 0 : (ynext >= NC ? NC - 1 : ynext);

    unsigned long long acc = 0ull;
    int s = 0, ph = 0;

    for (int k = 0; k < ROWS_PER_WARP; k++) {
        const int row = gw + k * TOTW;
        const int y = ynext;

        // Tt LDGs issued BEFORE the wait (L2 latency overlaps DRAM wait).
        const uint2* tt2 = reinterpret_cast<const uint2*>(g_Tth + (size_t)y * NC);
        uint2 tw[8];
#pragma unroll
        for (int j = 0; j < 8; j++) tw[j] = tt2[lane + 32 * j];

        // Prefetch next label (broadcast load, before the wait).
        if (k + 1 < ROWS_PER_WARP) {
            int i2 = gw + (k + 1) * TOTW;
            int yy = is64 ? (int)((const long long*)target)[i2]
                          : ((const int*)target)[i2];
            ynext = yy < 0 ? 0 : (yy >= NC ? NC - 1 : yy);
        }

        const unsigned int mb   = mb_base + s * 8;
        const char*        slot = &buf[warp][0][0] + s * SLOT_BYTES;
        mbar_wait(mb, ph);

        // Target logit: LDS broadcast (all lanes, same address, N=1).
        const float ly = *reinterpret_cast<const float*>(slot + (size_t)y * 4);

        // Fused Z / D from smem + Tt registers.
        const float4* r4 = reinterpret_cast<const float4*>(slot);
        float Z = 0.f, D = 0.f;
#pragma unroll
        for (int j = 0; j < 8; j++) {
            int idx = lane + 32 * j;
            if (idx < NC / 4) {
                float4 v = r4[idx];
                float e0 = __expf(v.x);
                float e1 = __expf(v.y);
                float e2 = __expf(v.z);
                float e3 = __expf(v.w);
                Z += (e0 + e1) + (e2 + e3);
                float2 t01 = __half22float2(*reinterpret_cast<__half2*>(&tw[j].x));
                float2 t23 = __half22float2(*reinterpret_cast<__half2*>(&tw[j].y));
                D = fmaf(e0, t01.x, fmaf(e1, t01.y, fmaf(e2, t23.x, fmaf(e3, t23.y, D))));
            }
        }
        // Two independent 5-step shuffle trees (latency overlaps).
#pragma unroll
        for (int o = 16; o > 0; o >>= 1) {
            Z += __shfl_xor_sync(0xffffffffu, Z, o);
            D += __shfl_xor_sync(0xffffffffu, D, o);
        }

        if (lane == 0) {
            float lse = __logf(Z);
            float ey  = __expf(ly);
            float val = (ey / D) * (lse - ly);   // beta * ce
            acc += (unsigned long long)__double2ll_rn((double)val * FIXSCALE);
        }

        // Recycle this slot (private to this warp): row k+DEPTH.
        if (lane == 0 && k + DEPTH < ROWS_PER_WARP)
            bulk_load(sb_base + s * SLOT_BYTES,
                      logits + (size_t)(row + DEPTH * TOTW) * NC, SLOT_BYTES, mb);

        if (++s == DEPTH) { s = 0; ph ^= 1; }
    }

    // CTA epilogue: deterministic integer reduction.
    if (lane == 0) s_part[warp] = acc;
    __syncthreads();
    if (tid == 0) {
        unsigned long long tot = 0ull;
#pragma unroll
        for (int w = 0; w < WARPS_PER_CTA; w++) tot += s_part[w];
        atomicAdd(&g_sum, tot);
        __threadfence();
        unsigned int ticket = atomicAdd(&g_done, 1u);
        if (ticket == (unsigned)(gridDim.x - 1)) {
            unsigned long long v = atomicAdd(&g_sum, 0ull);
            outp[0] = (float)((double)v / FIXSCALE / (double)NROWS);
        }
    }
}

extern "C" void kernel_launch(void* const* d_in, const int* in_sizes, int n_in,
                              void* d_out, int out_size) {
    const float* logits = (const float*)d_in[0];   // [N, C] f32
    const float* T      = (const float*)d_in[1];   // [C, C] f32
    const void*  target = d_in[2];                 // [N] int32 or int64
    float*       out    = (float*)d_out;

    prep_k<<<1025, 256>>>(T, (const uint4*)target);
    row_k<<<GRID_ROWK, 128>>>(logits, target, out);
}

// round 15
// speedup vs baseline: 1.1179x; 1.0010x over previous
#include <cuda_runtime.h>
#include <cuda_fp16.h>
#include <math.h>

#define NROWS 32768
#define NC 1000
#define SLOT_BYTES 4000          // one row of logits
#define DEPTH 2                  // per-warp pipeline depth
#define WARPS_PER_CTA 4
#define GRID_ROWK 1024           // 4096 warps x 8 rows; 7 CTAs/SM
#define TOTW (GRID_ROWK * WARPS_PER_CTA)
#define ROWS_PER_WARP (NROWS / TOTW)   // 8
#define FIXSCALE 268435456.0     // 2^28

// Scratch (allocation-free device globals, zero-initialized at module load).
// Tt padded for unpredicated loads. g_sum/g_done self-reset each invocation.
__device__ __align__(16) __half g_Tth[NC * NC + 32];
__device__ unsigned long long g_sum;
__device__ unsigned int g_done;

// ---------------------------------------------------------------------------
// Kernel 1: pure transpose T -> fp16 (1024 CTAs, one 32x32 tile each).
// Triggers programmatic launch completion immediately so row_k's prologue
// overlaps the transpose.
// ---------------------------------------------------------------------------
__global__ __launch_bounds__(256) void prep_k(const float* __restrict__ T) {
    cudaTriggerProgrammaticLaunchCompletion();
    __shared__ float tile[32][33];
    const int bx = blockIdx.x & 31, by = blockIdx.x >> 5;
    const int tx = threadIdx.x & 31, ty = threadIdx.x >> 5;
    int x = bx * 32 + tx;
#pragma unroll
    for (int j = 0; j < 32; j += 8) {
        int y = by * 32 + ty + j;
        if (x < NC && y < NC)
            tile[ty + j][tx] = T[y * NC + x];
    }
    __syncthreads();
    int x2 = by * 32 + tx;
#pragma unroll
    for (int j = 0; j < 32; j += 8) {
        int y2 = bx * 32 + ty + j;
        if (x2 < NC && y2 < NC)
            g_Tth[(size_t)y2 * NC + x2] = __float2half_rn(tile[tx][ty + j]);
    }
}

// ---------------------------------------------------------------------------
// helpers
// ---------------------------------------------------------------------------
__device__ __forceinline__ unsigned int smem_u32(const void* p) {
    unsigned int a;
    asm("{ .reg .u64 t; cvta.to.shared.u64 t, %1; cvt.u32.u64 %0, t; }"
        : "=r"(a) : "l"(p));
    return a;
}
__device__ __forceinline__ void mbar_init(unsigned int mbar, unsigned int cnt) {
    asm volatile("mbarrier.init.shared.b64 [%0], %1;" :: "r"(mbar), "r"(cnt) : "memory");
}
__device__ __forceinline__ void mbar_wait(unsigned int mbar, int phase) {
    asm volatile(
        "{\n\t.reg .pred P;\n\t"
        "W_%=: mbarrier.try_wait.parity.acquire.cta.shared::cta.b64 P, [%0], %1, 0x989680;\n\t"
        "@P bra D_%=;\n\t"
        "bra W_%=;\n\t"
        "D_%=:\n\t}"
        :: "r"(mbar), "r"(phase) : "memory");
}
__device__ __forceinline__ void bulk_load(unsigned int dst, const void* src,
                                          unsigned int bytes, unsigned int mbar) {
    asm volatile("mbarrier.arrive.expect_tx.shared.b64 _, [%0], %1;"
                 :: "r"(mbar), "r"(bytes) : "memory");
    asm volatile(
        "cp.async.bulk.shared::cluster.global.mbarrier::complete_tx::bytes "
        "[%0], [%1], %2, [%3];"
        :: "r"(dst), "l"(src), "r"(bytes), "r"(mbar) : "memory");
}

// ---------------------------------------------------------------------------
// Kernel 2 (PDL secondary): per-warp depth-2 pipelines at 7 CTAs/SM.
// Prologue (mbar init, bulk loads, dtype detect, first label) runs BEFORE
// cudaGridDependencySynchronize(); only the first g_Tth read is gated.
// ---------------------------------------------------------------------------
__global__ __launch_bounds__(128) void row_k(const float* __restrict__ logits,
                                             const void* __restrict__ target,
                                             float* __restrict__ outp) {
    __shared__ __align__(128) char buf[WARPS_PER_CTA][DEPTH][SLOT_BYTES];
    __shared__ __align__(8) unsigned long long mbars[WARPS_PER_CTA][DEPTH];
    __shared__ unsigned long long s_part[WARPS_PER_CTA];

    const int tid  = threadIdx.x;
    const int lane = tid & 31;
    const int warp = tid >> 5;
    const int gw   = blockIdx.x * WARPS_PER_CTA + warp;

    const unsigned int mb_base = smem_u32(&mbars[warp][0]);
    const unsigned int sb_base = smem_u32(&buf[warp][0][0]);

    if (tid < WARPS_PER_CTA * DEPTH)
        mbar_init(smem_u32(&mbars[tid / DEPTH][tid % DEPTH]), 1);
    __syncthreads();

    // Prologue: lane 0 fills both slots (independent of g_Tth).
    if (lane == 0) {
#pragma unroll
        for (int s = 0; s < DEPTH; s++)
            bulk_load(sb_base + s * SLOT_BYTES,
                      logits + (size_t)(gw + s * TOTW) * NC, SLOT_BYTES,
                      mb_base + s * 8);
    }

    // Per-warp dtype detect: int64 little-endian labels < 2^31 -> odd 32-bit
    // words of the first 8 labels are all zero (broadcast loads, 2 sectors).
    const uint4* t4 = (const uint4*)target;
    uint4 da = t4[0], db = t4[1];
    const int is64 = ((da.y | da.w | db.y | db.w) == 0u) ? 1 : 0;

    // Label for k=0 (broadcast load).
    int ynext = is64 ? (int)((const long long*)target)[gw]
                     : ((const int*)target)[gw];
    ynext = ynext < 0 ? 0 : (ynext >= NC ? NC - 1 : ynext);

    // Gate on prep_k completion before the first g_Tth read.
    cudaGridDependencySynchronize();

    unsigned long long acc = 0ull;
    int s = 0, ph = 0;

    for (int k = 0; k < ROWS_PER_WARP; k++) {
        const int row = gw + k * TOTW;
        const int y = ynext;

        // Tt LDGs issued BEFORE the wait (L2 latency overlaps DRAM wait).
        const uint2* tt2 = reinterpret_cast<const uint2*>(g_Tth + (size_t)y * NC);
        uint2 tw[8];
#pragma unroll
        for (int j = 0; j < 8; j++) tw[j] = tt2[lane + 32 * j];

        // Prefetch next label (broadcast load, before the wait).
        if (k + 1 < ROWS_PER_WARP) {
            int i2 = gw + (k + 1) * TOTW;
            int yy = is64 ? (int)((const long long*)target)[i2]
                          : ((const int*)target)[i2];
            ynext = yy < 0 ? 0 : (yy >= NC ? NC - 1 : yy);
        }

        const unsigned int mb   = mb_base + s * 8;
        const char*        slot = &buf[warp][0][0] + s * SLOT_BYTES;
        mbar_wait(mb, ph);

        // Target logit: LDS broadcast (all lanes, same address, N=1).
        const float ly = *reinterpret_cast<const float*>(slot + (size_t)y * 4);

        // Fused Z / D from smem + Tt registers.
        const float4* r4 = reinterpret_cast<const float4*>(slot);
        float Z = 0.f, D = 0.f;
#pragma unroll
        for (int j = 0; j < 8; j++) {
            int idx = lane + 32 * j;
            if (idx < NC / 4) {
                float4 v = r4[idx];
                float e0 = __expf(v.x);
                float e1 = __expf(v.y);
                float e2 = __expf(v.z);
                float e3 = __expf(v.w);
                Z += (e0 + e1) + (e2 + e3);
                float2 t01 = __half22float2(*reinterpret_cast<__half2*>(&tw[j].x));
                float2 t23 = __half22float2(*reinterpret_cast<__half2*>(&tw[j].y));
                D = fmaf(e0, t01.x, fmaf(e1, t01.y, fmaf(e2, t23.x, fmaf(e3, t23.y, D))));
            }
        }
#pragma unroll
        for (int o = 16; o > 0; o >>= 1) {
            Z += __shfl_xor_sync(0xffffffffu, Z, o);
            D += __shfl_xor_sync(0xffffffffu, D, o);
        }

        if (lane == 0) {
            float lse = __logf(Z);
            float ey  = __expf(ly);
            float val = (ey / D) * (lse - ly);   // beta * ce
            acc += (unsigned long long)__double2ll_rn((double)val * FIXSCALE);
        }

        // Recycle this slot (private to this warp): row k+DEPTH.
        if (lane == 0 && k + DEPTH < ROWS_PER_WARP)
            bulk_load(sb_base + s * SLOT_BYTES,
                      logits + (size_t)(row + DEPTH * TOTW) * NC, SLOT_BYTES, mb);

        if (++s == DEPTH) { s = 0; ph ^= 1; }
    }

    // CTA epilogue: deterministic integer reduction + self-reset of globals.
    if (lane == 0) s_part[warp] = acc;
    __syncthreads();
    if (tid == 0) {
        unsigned long long tot = 0ull;
#pragma unroll
        for (int w = 0; w < WARPS_PER_CTA; w++) tot += s_part[w];
        atomicAdd(&g_sum, tot);
        __threadfence();
        unsigned int ticket = atomicAdd(&g_done, 1u);
        if (ticket == (unsigned)(gridDim.x - 1)) {
            unsigned long long v = atomicAdd(&g_sum, 0ull);
            outp[0] = (float)((double)v / FIXSCALE / (double)NROWS);
            g_sum = 0ull;     // reset for next graph replay
            g_done = 0u;      // (kernel boundary publishes these)
        }
    }
}

extern "C" void kernel_launch(void* const* d_in, const int* in_sizes, int n_in,
                              void* d_out, int out_size) {
    const float* logits = (const float*)d_in[0];   // [N, C] f32
    const float* T      = (const float*)d_in[1];   // [C, C] f32
    const void*  target = d_in[2];                 // [N] int32 or int64
    float*       out    = (float*)d_out;

    prep_k<<<1024, 256>>>(T);

    // PDL secondary: may start while prep_k runs; gated in-kernel by
    // cudaGridDependencySynchronize().
    cudaLaunchConfig_t cfg = {};
    cfg.gridDim  = dim3(GRID_ROWK, 1, 1);
    cfg.blockDim = dim3(128, 1, 1);
    cfg.dynamicSmemBytes = 0;
    cfg.stream = 0;
    cudaLaunchAttribute attrs[1];
    attrs[0].id = cudaLaunchAttributeProgrammaticStreamSerialization;
    attrs[0].val.programmaticStreamSerializationAllowed = 1;
    cfg.attrs = attrs;
    cfg.numAttrs = 1;
    cudaLaunchKernelEx(&cfg, row_k, logits, target, out);
}

// round 16
// speedup vs baseline: 1.1191x; 1.0010x over previous
#include <cuda_runtime.h>
#include <cuda_fp16.h>
#include <math.h>

#define NROWS 32768
#define NC 1000
#define SLOT_BYTES 4000          // one row of logits
#define DEPTH 2                  // per-warp pipeline depth
#define WARPS_PER_CTA 4
#define GRID_ROWK 1024           // 4096 warps x 8 rows; 7 CTAs/SM
#define TOTW (GRID_ROWK * WARPS_PER_CTA)
#define ROWS_PER_WARP (NROWS / TOTW)   // 8
#define FIXSCALE 268435456.0     // 2^28

// Scratch (allocation-free device globals, zero-initialized at module load).
// Tt padded for unpredicated loads. g_sum/g_done self-reset each invocation.
__device__ __align__(16) __half g_Tth[NC * NC + 32];
__device__ unsigned long long g_sum;
__device__ unsigned int g_done;

// ---------------------------------------------------------------------------
// Kernel 1: pure transpose T -> fp16 (1024 CTAs, one 32x32 tile each).
// ---------------------------------------------------------------------------
__global__ __launch_bounds__(256) void prep_k(const float* __restrict__ T) {
    cudaTriggerProgrammaticLaunchCompletion();
    __shared__ float tile[32][33];
    const int bx = blockIdx.x & 31, by = blockIdx.x >> 5;
    const int tx = threadIdx.x & 31, ty = threadIdx.x >> 5;
    int x = bx * 32 + tx;
#pragma unroll
    for (int j = 0; j < 32; j += 8) {
        int y = by * 32 + ty + j;
        if (x < NC && y < NC)
            tile[ty + j][tx] = T[y * NC + x];
    }
    __syncthreads();
    int x2 = by * 32 + tx;
#pragma unroll
    for (int j = 0; j < 32; j += 8) {
        int y2 = bx * 32 + ty + j;
        if (x2 < NC && y2 < NC)
            g_Tth[(size_t)y2 * NC + x2] = __float2half_rn(tile[tx][ty + j]);
    }
}

// ---------------------------------------------------------------------------
// helpers
// ---------------------------------------------------------------------------
__device__ __forceinline__ unsigned int smem_u32(const void* p) {
    unsigned int a;
    asm("{ .reg .u64 t; cvta.to.shared.u64 t, %1; cvt.u32.u64 %0, t; }"
        : "=r"(a) : "l"(p));
    return a;
}
__device__ __forceinline__ void mbar_init(unsigned int mbar, unsigned int cnt) {
    asm volatile("mbarrier.init.shared.b64 [%0], %1;" :: "r"(mbar), "r"(cnt) : "memory");
}
__device__ __forceinline__ void mbar_wait(unsigned int mbar, int phase) {
    asm volatile(
        "{\n\t.reg .pred P;\n\t"
        "W_%=: mbarrier.try_wait.parity.acquire.cta.shared::cta.b64 P, [%0], %1, 0x989680;\n\t"
        "@P bra D_%=;\n\t"
        "bra W_%=;\n\t"
        "D_%=:\n\t}"
        :: "r"(mbar), "r"(phase) : "memory");
}
__device__ __forceinline__ void bulk_load(unsigned int dst, const void* src,
                                          unsigned int bytes, unsigned int mbar) {
    asm volatile("mbarrier.arrive.expect_tx.shared.b64 _, [%0], %1;"
                 :: "r"(mbar), "r"(bytes) : "memory");
    asm volatile(
        "cp.async.bulk.shared::cluster.global.mbarrier::complete_tx::bytes "
        "[%0], [%1], %2, [%3];"
        :: "r"(dst), "l"(src), "r"(bytes), "r"(mbar) : "memory");
}

// ---------------------------------------------------------------------------
// Kernel 2 (PDL secondary): per-warp depth-2 pipelines at 7 CTAs/SM.
// D accumulated in packed fp16 (HFMA2 against the raw half2 Tt data);
// 8-term chains per lane-half, cross-lane reduction in fp32.
// ---------------------------------------------------------------------------
__global__ __launch_bounds__(128) void row_k(const float* __restrict__ logits,
                                             const void* __restrict__ target,
                                             float* __restrict__ outp) {
    __shared__ __align__(128) char buf[WARPS_PER_CTA][DEPTH][SLOT_BYTES];
    __shared__ __align__(8) unsigned long long mbars[WARPS_PER_CTA][DEPTH];
    __shared__ unsigned long long s_part[WARPS_PER_CTA];

    const int tid  = threadIdx.x;
    const int lane = tid & 31;
    const int warp = tid >> 5;
    const int gw   = blockIdx.x * WARPS_PER_CTA + warp;

    const unsigned int mb_base = smem_u32(&mbars[warp][0]);
    const unsigned int sb_base = smem_u32(&buf[warp][0][0]);

    if (tid < WARPS_PER_CTA * DEPTH)
        mbar_init(smem_u32(&mbars[tid / DEPTH][tid % DEPTH]), 1);
    __syncthreads();

    // Prologue: lane 0 fills both slots (independent of g_Tth).
    if (lane == 0) {
#pragma unroll
        for (int s = 0; s < DEPTH; s++)
            bulk_load(sb_base + s * SLOT_BYTES,
                      logits + (size_t)(gw + s * TOTW) * NC, SLOT_BYTES,
                      mb_base + s * 8);
    }

    // Per-warp dtype detect on the first 8 labels (broadcast loads).
    const uint4* t4 = (const uint4*)target;
    uint4 da = t4[0], db = t4[1];
    const int is64 = ((da.y | da.w | db.y | db.w) == 0u) ? 1 : 0;

    // Label for k=0 (broadcast load).
    int ynext = is64 ? (int)((const long long*)target)[gw]
                     : ((const int*)target)[gw];
    ynext = ynext < 0 ? 0 : (ynext >= NC ? NC - 1 : ynext);

    // Gate on prep_k completion before the first g_Tth read.
    cudaGridDependencySynchronize();

    unsigned long long acc = 0ull;
    int s = 0, ph = 0;

    for (int k = 0; k < ROWS_PER_WARP; k++) {
        const int row = gw + k * TOTW;
        const int y = ynext;

        // Tt LDGs issued BEFORE the wait (L2 latency overlaps DRAM wait).
        const uint2* tt2 = reinterpret_cast<const uint2*>(g_Tth + (size_t)y * NC);
        uint2 tw[8];
#pragma unroll
        for (int j = 0; j < 8; j++) tw[j] = tt2[lane + 32 * j];

        // Prefetch next label (broadcast load, before the wait).
        if (k + 1 < ROWS_PER_WARP) {
            int i2 = gw + (k + 1) * TOTW;
            int yy = is64 ? (int)((const long long*)target)[i2]
                          : ((const int*)target)[i2];
            ynext = yy < 0 ? 0 : (yy >= NC ? NC - 1 : yy);
        }

        const unsigned int mb   = mb_base + s * 8;
        const char*        slot = &buf[warp][0][0] + s * SLOT_BYTES;
        mbar_wait(mb, ph);

        // Target logit: LDS broadcast (all lanes, same address, N=1).
        const float ly = *reinterpret_cast<const float*>(slot + (size_t)y * 4);

        // Fused Z (fp32) / D (packed fp16) from smem + raw half2 Tt.
        const float4* r4 = reinterpret_cast<const float4*>(slot);
        float Z = 0.f;
        __half2 D2 = __float2half2_rn(0.f);
#pragma unroll
        for (int j = 0; j < 8; j++) {
            int idx = lane + 32 * j;
            if (idx < NC / 4) {
                float4 v = r4[idx];
                float e0 = __expf(v.x);
                float e1 = __expf(v.y);
                float e2 = __expf(v.z);
                float e3 = __expf(v.w);
                Z += (e0 + e1) + (e2 + e3);
                __half2 eh01 = __floats2half2_rn(e0, e1);   // cvt.rn.f16x2.f32
                __half2 eh23 = __floats2half2_rn(e2, e3);
                __half2 t01 = *reinterpret_cast<__half2*>(&tw[j].x);
                __half2 t23 = *reinterpret_cast<__half2*>(&tw[j].y);
                D2 = __hfma2(eh01, t01, __hfma2(eh23, t23, D2));
            }
        }
        float2 dd = __half22float2(D2);
        float D = dd.x + dd.y;
#pragma unroll
        for (int o = 16; o > 0; o >>= 1) {
            Z += __shfl_xor_sync(0xffffffffu, Z, o);
            D += __shfl_xor_sync(0xffffffffu, D, o);
        }

        if (lane == 0) {
            float lse = __logf(Z);
            float ey  = __expf(ly);
            float val = (ey / D) * (lse - ly);   // beta * ce
            acc += (unsigned long long)__double2ll_rn((double)val * FIXSCALE);
        }

        // Recycle this slot (private to this warp): row k+DEPTH.
        if (lane == 0 && k + DEPTH < ROWS_PER_WARP)
            bulk_load(sb_base + s * SLOT_BYTES,
                      logits + (size_t)(row + DEPTH * TOTW) * NC, SLOT_BYTES, mb);

        if (++s == DEPTH) { s = 0; ph ^= 1; }
    }

    // CTA epilogue: deterministic integer reduction + self-reset of globals.
    if (lane == 0) s_part[warp] = acc;
    __syncthreads();
    if (tid == 0) {
        unsigned long long tot = 0ull;
#pragma unroll
        for (int w = 0; w < WARPS_PER_CTA; w++) tot += s_part[w];
        atomicAdd(&g_sum, tot);
        __threadfence();
        unsigned int ticket = atomicAdd(&g_done, 1u);
        if (ticket == (unsigned)(gridDim.x - 1)) {
            unsigned long long v = atomicAdd(&g_sum, 0ull);
            outp[0] = (float)((double)v / FIXSCALE / (double)NROWS);
            g_sum = 0ull;     // reset for next graph replay
            g_done = 0u;
        }
    }
}

extern "C" void kernel_launch(void* const* d_in, const int* in_sizes, int n_in,
                              void* d_out, int out_size) {
    const float* logits = (const float*)d_in[0];   // [N, C] f32
    const float* T      = (const float*)d_in[1];   // [C, C] f32
    const void*  target = d_in[2];                 // [N] int32 or int64
    float*       out    = (float*)d_out;

    prep_k<<<1024, 256>>>(T);

    cudaLaunchConfig_t cfg = {};
    cfg.gridDim  = dim3(GRID_ROWK, 1, 1);
    cfg.blockDim = dim3(128, 1, 1);
    cfg.dynamicSmemBytes = 0;
    cfg.stream = 0;
    cudaLaunchAttribute attrs[1];
    attrs[0].id = cudaLaunchAttributeProgrammaticStreamSerialization;
    attrs[0].val.programmaticStreamSerializationAllowed = 1;
    cfg.attrs = attrs;
    cfg.numAttrs = 1;
    cudaLaunchKernelEx(&cfg, row_k, logits, target, out);
}